// round 13
// baseline (speedup 1.0000x reference)
#include <cuda_runtime.h>
#include <cuda_fp16.h>
#include <cstdint>

#define NTOK 4096
#define DIM  1024
#define HID  2048
#define NEXP 8
#define VOC  32000
#define LN_EPS 1e-5f
#define GEMM_SMEM (1024 + 2 * 32 * 1024)   // rows[]/pad + 2 stages * (A 16K + B 16K)

// ---------------- device-global scratch ----------------
__device__ __half g_hh [(size_t)NTOK * DIM];            // embeddings fp16
__device__ __half g_ah [(size_t)NTOK * 2 * HID];        // expert act fp16 per slot
__device__ float  g_y  [(size_t)NTOK * DIM];            // gate-combined expert out (fp32)
__device__ __half g_ynh[(size_t)NTOK * DIM];            // layernormed fp16
__device__ __half g_Whf[(size_t)VOC * DIM];             // head_W fp16
__device__ __half g_W1h[(size_t)NEXP * HID * DIM];      // W1^T fp16 [E][N][K]
__device__ __half g_W2h[(size_t)NEXP * DIM * HID];      // W2^T fp16 [E][N][K]
__device__ float g_tv[NTOK * 2];
__device__ int   g_list[NEXP * NTOK];
__device__ int   g_count[NEXP];                         // zeroed at end of combine_ln

// ---------------- helpers ----------------
__device__ __forceinline__ uint32_t sw128(uint32_t o) { return o ^ ((o >> 3) & 0x70); }
__device__ __forceinline__ void cpa16(uint32_t d, const void* s) {
    asm volatile("cp.async.cg.shared.global [%0], [%1], 16;" :: "r"(d), "l"(s));
}
__device__ __forceinline__ void ldmx4(uint32_t* r, uint32_t a) {
    asm volatile("ldmatrix.sync.aligned.m8n8.x4.shared.b16 {%0,%1,%2,%3}, [%4];"
                 : "=r"(r[0]), "=r"(r[1]), "=r"(r[2]), "=r"(r[3]) : "r"(a));
}
__device__ __forceinline__ void mma_hf(float* c, const uint32_t* a, const uint32_t* b) {
    asm volatile("mma.sync.aligned.m16n8k16.row.col.f32.f16.f16.f32 "
                 "{%0,%1,%2,%3},{%4,%5,%6,%7},{%8,%9},{%0,%1,%2,%3};"
                 : "+f"(c[0]), "+f"(c[1]), "+f"(c[2]), "+f"(c[3])
                 : "r"(a[0]), "r"(a[1]), "r"(a[2]), "r"(a[3]), "r"(b[0]), "r"(b[1]));
}

// ---------------- small kernels ----------------
__global__ void conv_half_kernel(const float4* __restrict__ in, long n4) {
    long i = (long)blockIdx.x * blockDim.x + threadIdx.x;
    if (i >= n4) return;
    float4 v = in[i];
    __half2* o = (__half2*)g_Whf;
    o[i*2+0] = __floats2half2_rn(v.x, v.y);
    o[i*2+1] = __floats2half2_rn(v.z, v.w);
}

// in: [E][K][N] fp32 -> out fp16: [E][N][K]
template<int WSEL>
__global__ void conv_transpose_kernel(const float* __restrict__ in, int K, int N) {
    __shared__ float t[32][33];
    const int e = blockIdx.z;
    const float* pin = in + (size_t)e * K * N;
    __half* ph = (WSEL == 1 ? g_W1h : g_W2h) + (size_t)e * K * N;
    const int nb = blockIdx.x * 32, kb = blockIdx.y * 32;
    const int tx = threadIdx.x, ty = threadIdx.y;
    #pragma unroll
    for (int i = 0; i < 32; i += 8)
        t[ty + i][tx] = pin[(size_t)(kb + ty + i) * N + nb + tx];
    __syncthreads();
    #pragma unroll
    for (int i = 0; i < 32; i += 8)
        ph[(size_t)(nb + ty + i) * K + kb + tx] = __float2half(t[tx][ty + i]);
}

// embed + gate softmax + top2 + scatter; also zeroes this token's g_y row
__global__ void embed_gate_kernel(const int* __restrict__ x,
                                  const float* __restrict__ embed_W,
                                  const float* __restrict__ gate_W,
                                  const float* __restrict__ gate_b,
                                  float* __restrict__ out, int write_idx) {
    __shared__ float sh[DIM];
    __shared__ float slogit[NEXP];
    const int n = blockIdx.x, tid = threadIdx.x;
    const float* erow = embed_W + (size_t)x[n] * DIM;
    float4 z4 = make_float4(0.f, 0.f, 0.f, 0.f);
    #pragma unroll
    for (int q = 0; q < DIM / 256; ++q) {
        int d = tid + q * 256;
        float v = erow[d];
        sh[d] = v;
        g_hh[(size_t)n * DIM + d] = __float2half(v);
    }
    *(float4*)(g_y + (size_t)n * DIM + tid * 4) = z4;
    __syncthreads();
    const int w = tid >> 5, lane = tid & 31;
    const float* gw = gate_W + (size_t)w * DIM;
    float acc = 0.f;
    for (int d = lane; d < DIM; d += 32) acc = fmaf(sh[d], gw[d], acc);
    #pragma unroll
    for (int o = 16; o > 0; o >>= 1) acc += __shfl_xor_sync(0xffffffffu, acc, o);
    if (lane == 0) slogit[w] = acc + gate_b[w];
    __syncthreads();
    if (tid == 0) {
        float mx = slogit[0];
        #pragma unroll
        for (int e = 1; e < NEXP; ++e) mx = fmaxf(mx, slogit[e]);
        float p[NEXP], s = 0.f;
        #pragma unroll
        for (int e = 0; e < NEXP; ++e) { p[e] = expf(slogit[e] - mx); s += p[e]; }
        float inv = 1.f / s;
        #pragma unroll
        for (int e = 0; e < NEXP; ++e) p[e] *= inv;
        int i0 = 0; float v0 = p[0];
        #pragma unroll
        for (int e = 1; e < NEXP; ++e) if (p[e] > v0) { v0 = p[e]; i0 = e; }
        int i1 = -1; float v1 = -1.f;
        #pragma unroll
        for (int e = 0; e < NEXP; ++e) {
            if (e != i0 && p[e] > v1) { v1 = p[e]; i1 = e; }
        }
        g_tv[n*2+0] = v0; g_tv[n*2+1] = v1;
        int p0 = atomicAdd(&g_count[i0], 1); g_list[i0 * NTOK + p0] = n*2;
        int p1 = atomicAdd(&g_count[i1], 1); g_list[i1 * NTOK + p1] = n*2+1;
        if (write_idx) {
            out[(size_t)NTOK * VOC + n*2+0] = (float)i0;
            out[(size_t)NTOK * VOC + n*2+1] = (float)i1;
        }
    }
}

// ---------------- expert HMMA GEMM: 128x128 CTA, 4 warps (warp 64x64), 3 CTA/SM ----
// K-chunk 64, 2-stage cp.async. 128 B/MMA smem traffic (vs 192 at 32x64 warp tile).
// MODE 1: relu(h W1+b1) -> g_ah fp16
// MODE 2: (a W2 + b2) * tv[slot]  --RED.ADD--> g_y[token]
template<int MODE, int KTOT, int NTOT>
__global__ void __launch_bounds__(128, 3) moe_mma_kernel(const float* __restrict__ bias) {
    constexpr int NCHUNK = KTOT / 64;
    extern __shared__ char smem[];
    const int tid = threadIdx.x;

    const int mt = blockIdx.y, nt = blockIdx.x, e = blockIdx.z;
    if (mt * 128 >= g_count[e]) return;
    const int rowBase = mt * 128, nBase = nt * 128;
    const uint32_t sb = (uint32_t)__cvta_generic_to_shared(smem);
    int* rows = (int*)smem;
    {
        int r = rowBase + tid;
        rows[tid] = (r < g_count[e]) ? g_list[e * NTOK + r] : -1;
    }
    __syncthreads();

    const __half* A = (MODE == 1) ? g_hh : g_ah;
    const __half* B = ((MODE == 1) ? g_W1h : g_W2h)
                      + (size_t)e * KTOT * NTOT + (size_t)nBase * KTOT;

    auto load_stage = [&](int st, int chunk) {
        const uint32_t stb = sb + 1024 + st * 32768;
        const int k0 = chunk * 64;
        #pragma unroll
        for (int t = 0; t < 8; ++t) {
            int c = tid + t * 128, r = c >> 3, q = c & 7;
            int s = rows[r]; if (s < 0) s = rows[0];
            size_t ro = (MODE == 1 ? (size_t)(s >> 1) : (size_t)s) * KTOT + k0 + q * 8;
            uint32_t so = sw128((uint32_t)(r * 128 + q * 16));
            cpa16(stb + so,         A + ro);
            cpa16(stb + 16384 + so, B + (size_t)r * KTOT + k0 + q * 8);
        }
    };

    const int lane = tid & 31, wid = tid >> 5;          // 4 warps: 2m x 2n
    const int wm = (wid & 1) * 64, wn = (wid >> 1) * 64;
    const uint32_t aoff = (uint32_t)((wm + (lane & 15)) * 128 + (lane >> 4) * 16);
    const uint32_t boff0 = (uint32_t)((wn + ((lane >> 4) << 3) + (lane & 7)) * 128 +
                                      ((lane >> 3) & 1) * 16);

    float acc[4][8][4];
    #pragma unroll
    for (int i = 0; i < 4; ++i)
        #pragma unroll
        for (int j = 0; j < 8; ++j)
            #pragma unroll
            for (int k = 0; k < 4; ++k) acc[i][j][k] = 0.f;

    load_stage(0, 0); asm volatile("cp.async.commit_group;");

    for (int it = 0; it < NCHUNK; ++it) {
        asm volatile("cp.async.wait_group 0;");
        __syncthreads();
        if (it + 1 < NCHUNK) load_stage((it + 1) & 1, it + 1);
        asm volatile("cp.async.commit_group;");
        const uint32_t stb = sb + 1024 + (it & 1) * 32768;
        #pragma unroll
        for (int ks = 0; ks < 4; ++ks) {
            const uint32_t kb = ks * 32;
            uint32_t a[4][4], b[8][2];
            #pragma unroll
            for (int mi = 0; mi < 4; ++mi)
                ldmx4(a[mi], stb + sw128(aoff + mi * 16 * 128 + kb));
            #pragma unroll
            for (int nj = 0; nj < 4; ++nj) {
                uint32_t r[4];
                ldmx4(r, stb + 16384 + sw128(boff0 + nj * 16 * 128 + kb));
                b[nj*2][0] = r[0]; b[nj*2][1] = r[1];
                b[nj*2+1][0] = r[2]; b[nj*2+1][1] = r[3];
            }
            #pragma unroll
            for (int mi = 0; mi < 4; ++mi)
                #pragma unroll
                for (int nf = 0; nf < 8; ++nf)
                    mma_hf(acc[mi][nf], a[mi], b[nf]);
        }
    }

    #pragma unroll
    for (int mi = 0; mi < 4; ++mi) {
        #pragma unroll
        for (int h = 0; h < 2; ++h) {
            const int rl = wm + mi * 16 + (lane >> 2) + h * 8;
            const int slot = rows[rl];
            if (slot < 0) continue;
            #pragma unroll
            for (int nf = 0; nf < 8; ++nf) {
                const int gc = nBase + wn + nf * 8 + (lane & 3) * 2;
                const float v0 = acc[mi][nf][h*2], v1 = acc[mi][nf][h*2+1];
                if (MODE == 1) {
                    float a0 = v0 + bias[(size_t)e * HID + gc];
                    float a1 = v1 + bias[(size_t)e * HID + gc + 1];
                    a0 = a0 > 0.f ? a0 : 0.f;
                    a1 = a1 > 0.f ? a1 : 0.f;
                    *(__half2*)(g_ah + (size_t)slot * HID + gc) = __floats2half2_rn(a0, a1);
                } else {
                    const float tv = g_tv[slot];
                    float* yp = g_y + (size_t)(slot >> 1) * DIM + gc;
                    atomicAdd(yp + 0, (v0 + bias[(size_t)e * DIM + gc])     * tv);
                    atomicAdd(yp + 1, (v1 + bias[(size_t)e * DIM + gc + 1]) * tv);
                }
            }
        }
    }
}

// ---------------- head GEMM: same 4-warp/64x64 config, 3 CTA/SM ----------------
__global__ void __launch_bounds__(128, 3) head_mma_kernel(const float* __restrict__ bias,
                                                          float* __restrict__ outp) {
    constexpr int NCHUNK = DIM / 64;
    extern __shared__ char smem[];
    const int tid = threadIdx.x;
    const int rowBase = blockIdx.x * 128, nBase = blockIdx.y * 128;
    const uint32_t sb = (uint32_t)__cvta_generic_to_shared(smem);

    auto load_stage = [&](int st, int chunk) {
        const uint32_t stb = sb + 1024 + st * 32768;
        const int k0 = chunk * 64;
        #pragma unroll
        for (int t = 0; t < 8; ++t) {
            int c = tid + t * 128, r = c >> 3, q = c & 7;
            uint32_t so = sw128((uint32_t)(r * 128 + q * 16));
            cpa16(stb + so,         g_ynh + (size_t)(rowBase + r) * DIM + k0 + q * 8);
            cpa16(stb + 16384 + so, g_Whf + (size_t)(nBase + r) * DIM + k0 + q * 8);
        }
    };

    const int lane = tid & 31, wid = tid >> 5;
    const int wm = (wid & 1) * 64, wn = (wid >> 1) * 64;
    const uint32_t aoff = (uint32_t)((wm + (lane & 15)) * 128 + (lane >> 4) * 16);
    const uint32_t boff0 = (uint32_t)((wn + ((lane >> 4) << 3) + (lane & 7)) * 128 +
                                      ((lane >> 3) & 1) * 16);

    float acc[4][8][4];
    #pragma unroll
    for (int i = 0; i < 4; ++i)
        #pragma unroll
        for (int j = 0; j < 8; ++j)
            #pragma unroll
            for (int k = 0; k < 4; ++k) acc[i][j][k] = 0.f;

    load_stage(0, 0); asm volatile("cp.async.commit_group;");

    for (int it = 0; it < NCHUNK; ++it) {
        asm volatile("cp.async.wait_group 0;");
        __syncthreads();
        if (it + 1 < NCHUNK) load_stage((it + 1) & 1, it + 1);
        asm volatile("cp.async.commit_group;");
        const uint32_t stb = sb + 1024 + (it & 1) * 32768;
        #pragma unroll
        for (int ks = 0; ks < 4; ++ks) {
            const uint32_t kb = ks * 32;
            uint32_t a[4][4], b[8][2];
            #pragma unroll
            for (int mi = 0; mi < 4; ++mi)
                ldmx4(a[mi], stb + sw128(aoff + mi * 16 * 128 + kb));
            #pragma unroll
            for (int nj = 0; nj < 4; ++nj) {
                uint32_t r[4];
                ldmx4(r, stb + 16384 + sw128(boff0 + nj * 16 * 128 + kb));
                b[nj*2][0] = r[0]; b[nj*2][1] = r[1];
                b[nj*2+1][0] = r[2]; b[nj*2+1][1] = r[3];
            }
            #pragma unroll
            for (int mi = 0; mi < 4; ++mi)
                #pragma unroll
                for (int nf = 0; nf < 8; ++nf)
                    mma_hf(acc[mi][nf], a[mi], b[nf]);
        }
    }

    #pragma unroll
    for (int mi = 0; mi < 4; ++mi)
        #pragma unroll
        for (int h = 0; h < 2; ++h) {
            const int rl = wm + mi * 16 + (lane >> 2) + h * 8;
            #pragma unroll
            for (int nf = 0; nf < 8; ++nf) {
                const int gc = nBase + wn + nf * 8 + (lane & 3) * 2;
                float2 o = make_float2(acc[mi][nf][h*2]   + bias[gc],
                                       acc[mi][nf][h*2+1] + bias[gc+1]);
                *(float2*)(outp + (size_t)(rowBase + rl) * VOC + gc) = o;
            }
        }
}

// ---------------- LayerNorm on combined g_y (-> yn fp16); re-zeroes g_count ----------------
__global__ void combine_ln_kernel(const float* __restrict__ ln_g,
                                  const float* __restrict__ ln_b) {
    const int n = blockIdx.x, tid = threadIdx.x;
    const float* yrow = g_y + (size_t)n * DIM;
    float y[DIM / 256], s = 0.f, ss = 0.f;
    #pragma unroll
    for (int q = 0; q < DIM / 256; ++q) {
        int d = tid + q * 256;
        float v = yrow[d];
        y[q] = v; s += v; ss = fmaf(v, v, ss);
    }
    __shared__ float rs[8], rss[8];
    #pragma unroll
    for (int o = 16; o > 0; o >>= 1) {
        s  += __shfl_xor_sync(0xffffffffu, s, o);
        ss += __shfl_xor_sync(0xffffffffu, ss, o);
    }
    const int w = tid >> 5, lane = tid & 31;
    if (lane == 0) { rs[w] = s; rss[w] = ss; }
    __syncthreads();
    if (w == 0) {
        s  = (lane < 8) ? rs[lane]  : 0.f;
        ss = (lane < 8) ? rss[lane] : 0.f;
        #pragma unroll
        for (int o = 4; o > 0; o >>= 1) {
            s  += __shfl_xor_sync(0xffffffffu, s, o);
            ss += __shfl_xor_sync(0xffffffffu, ss, o);
        }
        if (lane == 0) { rs[0] = s; rss[0] = ss; }
    }
    __syncthreads();
    const float mu  = rs[0] * (1.f / DIM);
    const float var = rss[0] * (1.f / DIM) - mu * mu;
    const float inv = rsqrtf(var + LN_EPS);
    #pragma unroll
    for (int q = 0; q < DIM / 256; ++q) {
        int d = tid + q * 256;
        float v = fmaf((y[q] - mu) * inv, ln_g[d], ln_b[d]);
        g_ynh[(size_t)n * DIM + d] = __float2half(v);
    }
    if (n == 0 && tid < NEXP) g_count[tid] = 0;
}

// ---------------- launch: dual-stream event DAG (graph-capturable) ----------------
extern "C" void kernel_launch(void* const* d_in, const int* in_sizes, int n_in,
                              void* d_out, int out_size) {
    const int*   x       = (const int*)  d_in[0];
    const float* embed_W = (const float*)d_in[1];
    const float* gate_W  = (const float*)d_in[2];
    const float* gate_b  = (const float*)d_in[3];
    const float* W1      = (const float*)d_in[4];
    const float* b1      = (const float*)d_in[5];
    const float* W2      = (const float*)d_in[6];
    const float* b2      = (const float*)d_in[7];
    const float* ln_g    = (const float*)d_in[8];
    const float* ln_b    = (const float*)d_in[9];
    const float* head_W  = (const float*)d_in[10];
    const float* head_b  = (const float*)d_in[11];
    float* out = (float*)d_out;

    static cudaStream_t s2 = nullptr;
    static cudaEvent_t e0 = nullptr, e1 = nullptr, e2 = nullptr;
    static int init_done = 0;
    if (!init_done) {
        cudaFuncSetAttribute(moe_mma_kernel<1, DIM, HID>,
                             cudaFuncAttributeMaxDynamicSharedMemorySize, GEMM_SMEM);
        cudaFuncSetAttribute(moe_mma_kernel<2, HID, DIM>,
                             cudaFuncAttributeMaxDynamicSharedMemorySize, GEMM_SMEM);
        cudaFuncSetAttribute(head_mma_kernel,
                             cudaFuncAttributeMaxDynamicSharedMemorySize, GEMM_SMEM);
        cudaStreamCreateWithFlags(&s2, cudaStreamNonBlocking);
        cudaEventCreateWithFlags(&e0, cudaEventDisableTiming);
        cudaEventCreateWithFlags(&e1, cudaEventDisableTiming);
        cudaEventCreateWithFlags(&e2, cudaEventDisableTiming);
        init_done = 1;
    }

    const long long need_idx = (long long)NTOK * VOC + (long long)NTOK * 2;
    int write_idx = ((long long)out_size >= need_idx) ? 1 : 0;

    cudaEventRecord(e0, 0);
    cudaStreamWaitEvent(s2, e0, 0);

    conv_transpose_kernel<1><<<dim3(HID / 32, DIM / 32, NEXP), dim3(32, 8), 0, s2>>>(
        W1, DIM, HID);
    cudaEventRecord(e1, s2);
    conv_transpose_kernel<2><<<dim3(DIM / 32, HID / 32, NEXP), dim3(32, 8), 0, s2>>>(
        W2, HID, DIM);
    conv_half_kernel<<<(VOC * DIM / 4 + 255) / 256, 256, 0, s2>>>(
        (const float4*)head_W, (long)VOC * DIM / 4);
    cudaEventRecord(e2, s2);

    embed_gate_kernel<<<NTOK, 256>>>(x, embed_W, gate_W, gate_b, out, write_idx);

    cudaStreamWaitEvent(0, e1, 0);
    moe_mma_kernel<1, DIM, HID><<<dim3(HID / 128, NTOK / 128, NEXP), 128, GEMM_SMEM>>>(b1);

    cudaStreamWaitEvent(0, e2, 0);
    moe_mma_kernel<2, HID, DIM><<<dim3(DIM / 128, NTOK / 128, NEXP), 128, GEMM_SMEM>>>(b2);
    combine_ln_kernel<<<NTOK, 256>>>(ln_g, ln_b);
    head_mma_kernel<<<dim3(NTOK / 128, VOC / 128), 128, GEMM_SMEM>>>(head_b, out);
}

// round 14
// speedup vs baseline: 1.3631x; 1.3631x over previous
#include <cuda_runtime.h>
#include <cuda_fp16.h>
#include <cstdint>

#define NTOK 4096
#define DIM  1024
#define HID  2048
#define NEXP 8
#define VOC  32000
#define LN_EPS 1e-5f
#define GEMM_SMEM (1024 + 3 * 32 * 1024)   // rows[]/pad + 3 stages * (A 16K + B 16K)

// ---------------- device-global scratch ----------------
__device__ __half g_hh [(size_t)NTOK * DIM];            // embeddings fp16
__device__ __half g_ah [(size_t)NTOK * 2 * HID];        // expert act fp16 per slot
__device__ float  g_eo [(size_t)NTOK * 2 * DIM];        // expert out fp32 per slot
__device__ __half g_ynh[(size_t)NTOK * DIM];            // layernormed fp16
__device__ __half g_Whf[(size_t)VOC * DIM];             // head_W fp16
__device__ __half g_W1h[(size_t)NEXP * HID * DIM];      // W1^T fp16 [E][N][K]
__device__ __half g_W2h[(size_t)NEXP * DIM * HID];      // W2^T fp16 [E][N][K]
__device__ float g_tv[NTOK * 2];
__device__ int   g_list[NEXP * NTOK];
__device__ int   g_count[NEXP];                         // zeroed at end of combine_ln

// ---------------- helpers ----------------
__device__ __forceinline__ uint32_t sw128(uint32_t o) { return o ^ ((o >> 3) & 0x70); }
__device__ __forceinline__ void cpa16(uint32_t d, const void* s) {
    asm volatile("cp.async.cg.shared.global [%0], [%1], 16;" :: "r"(d), "l"(s));
}
__device__ __forceinline__ void ldmx4(uint32_t* r, uint32_t a) {
    asm volatile("ldmatrix.sync.aligned.m8n8.x4.shared.b16 {%0,%1,%2,%3}, [%4];"
                 : "=r"(r[0]), "=r"(r[1]), "=r"(r[2]), "=r"(r[3]) : "r"(a));
}
__device__ __forceinline__ void mma_hf(float* c, const uint32_t* a, const uint32_t* b) {
    asm volatile("mma.sync.aligned.m16n8k16.row.col.f32.f16.f16.f32 "
                 "{%0,%1,%2,%3},{%4,%5,%6,%7},{%8,%9},{%0,%1,%2,%3};"
                 : "+f"(c[0]), "+f"(c[1]), "+f"(c[2]), "+f"(c[3])
                 : "r"(a[0]), "r"(a[1]), "r"(a[2]), "r"(a[3]), "r"(b[0]), "r"(b[1]));
}

// ---------------- small kernels ----------------
__global__ void conv_half_kernel(const float4* __restrict__ in, long n4) {
    long i = (long)blockIdx.x * blockDim.x + threadIdx.x;
    if (i >= n4) return;
    float4 v = in[i];
    __half2* o = (__half2*)g_Whf;
    o[i*2+0] = __floats2half2_rn(v.x, v.y);
    o[i*2+1] = __floats2half2_rn(v.z, v.w);
}

// in: [E][K][N] fp32 -> out fp16: [E][N][K]
template<int WSEL>
__global__ void conv_transpose_kernel(const float* __restrict__ in, int K, int N) {
    __shared__ float t[32][33];
    const int e = blockIdx.z;
    const float* pin = in + (size_t)e * K * N;
    __half* ph = (WSEL == 1 ? g_W1h : g_W2h) + (size_t)e * K * N;
    const int nb = blockIdx.x * 32, kb = blockIdx.y * 32;
    const int tx = threadIdx.x, ty = threadIdx.y;
    #pragma unroll
    for (int i = 0; i < 32; i += 8)
        t[ty + i][tx] = pin[(size_t)(kb + ty + i) * N + nb + tx];
    __syncthreads();
    #pragma unroll
    for (int i = 0; i < 32; i += 8)
        ph[(size_t)(nb + ty + i) * K + kb + tx] = __float2half(t[tx][ty + i]);
}

__global__ void embed_gate_kernel(const int* __restrict__ x,
                                  const float* __restrict__ embed_W,
                                  const float* __restrict__ gate_W,
                                  const float* __restrict__ gate_b,
                                  float* __restrict__ out, int write_idx) {
    __shared__ float sh[DIM];
    __shared__ float slogit[NEXP];
    const int n = blockIdx.x, tid = threadIdx.x;
    const float* erow = embed_W + (size_t)x[n] * DIM;
    #pragma unroll
    for (int q = 0; q < DIM / 256; ++q) {
        int d = tid + q * 256;
        float v = erow[d];
        sh[d] = v;
        g_hh[(size_t)n * DIM + d] = __float2half(v);
    }
    __syncthreads();
    const int w = tid >> 5, lane = tid & 31;
    const float* gw = gate_W + (size_t)w * DIM;
    float acc = 0.f;
    for (int d = lane; d < DIM; d += 32) acc = fmaf(sh[d], gw[d], acc);
    #pragma unroll
    for (int o = 16; o > 0; o >>= 1) acc += __shfl_xor_sync(0xffffffffu, acc, o);
    if (lane == 0) slogit[w] = acc + gate_b[w];
    __syncthreads();
    if (tid == 0) {
        float mx = slogit[0];
        #pragma unroll
        for (int e = 1; e < NEXP; ++e) mx = fmaxf(mx, slogit[e]);
        float p[NEXP], s = 0.f;
        #pragma unroll
        for (int e = 0; e < NEXP; ++e) { p[e] = expf(slogit[e] - mx); s += p[e]; }
        float inv = 1.f / s;
        #pragma unroll
        for (int e = 0; e < NEXP; ++e) p[e] *= inv;
        int i0 = 0; float v0 = p[0];
        #pragma unroll
        for (int e = 1; e < NEXP; ++e) if (p[e] > v0) { v0 = p[e]; i0 = e; }
        int i1 = -1; float v1 = -1.f;
        #pragma unroll
        for (int e = 0; e < NEXP; ++e) {
            if (e != i0 && p[e] > v1) { v1 = p[e]; i1 = e; }
        }
        g_tv[n*2+0] = v0; g_tv[n*2+1] = v1;
        int p0 = atomicAdd(&g_count[i0], 1); g_list[i0 * NTOK + p0] = n*2;
        int p1 = atomicAdd(&g_count[i1], 1); g_list[i1 * NTOK + p1] = n*2+1;
        if (write_idx) {
            out[(size_t)NTOK * VOC + n*2+0] = (float)i0;
            out[(size_t)NTOK * VOC + n*2+1] = (float)i1;
        }
    }
}

// ---------------- expert HMMA GEMM (fp16 single-pass, fp32 accum) ----------------
// D tile 128x128, 8 warps (warp 32x64), K-chunk 64, 3-stage cp.async, 2 CTA/SM.
// MODE 1: relu(h W1+b1) -> g_ah fp16; MODE 2: a W2+b2 -> g_eo fp32
template<int MODE, int KTOT, int NTOT>
__global__ void __launch_bounds__(256, 2) moe_mma_kernel(const float* __restrict__ bias) {
    constexpr int NCHUNK = KTOT / 64;
    extern __shared__ char smem[];
    const int tid = threadIdx.x;

    const int mt = blockIdx.y, nt = blockIdx.x, e = blockIdx.z;
    if (mt * 128 >= g_count[e]) return;
    const int rowBase = mt * 128, nBase = nt * 128;
    const uint32_t sb = (uint32_t)__cvta_generic_to_shared(smem);
    int* rows = (int*)smem;
    if (tid < 128) {
        int r = rowBase + tid;
        rows[tid] = (r < g_count[e]) ? g_list[e * NTOK + r] : -1;
    }
    __syncthreads();

    const __half* A = (MODE == 1) ? g_hh : g_ah;
    const __half* B = ((MODE == 1) ? g_W1h : g_W2h)
                      + (size_t)e * KTOT * NTOT + (size_t)nBase * KTOT;

    auto load_stage = [&](int st, int chunk) {
        const uint32_t stb = sb + 1024 + st * 32768;
        const int k0 = chunk * 64;
        #pragma unroll
        for (int t = 0; t < 4; ++t) {
            int c = tid + t * 256, r = c >> 3, q = c & 7;
            int s = rows[r]; if (s < 0) s = rows[0];
            size_t ro = (MODE == 1 ? (size_t)(s >> 1) : (size_t)s) * KTOT + k0 + q * 8;
            uint32_t so = sw128((uint32_t)(r * 128 + q * 16));
            cpa16(stb + so,         A + ro);
            cpa16(stb + 16384 + so, B + (size_t)r * KTOT + k0 + q * 8);
        }
    };

    const int lane = tid & 31, wid = tid >> 5;
    const int wm = (wid & 3) * 32, wn = (wid >> 2) * 64;
    const uint32_t aoff = (uint32_t)((wm + (lane & 15)) * 128 + (lane >> 4) * 16);
    const uint32_t boff0 = (uint32_t)((wn + ((lane >> 4) << 3) + (lane & 7)) * 128 +
                                      ((lane >> 3) & 1) * 16);

    float acc[2][8][4];
    #pragma unroll
    for (int i = 0; i < 2; ++i)
        #pragma unroll
        for (int j = 0; j < 8; ++j)
            #pragma unroll
            for (int k = 0; k < 4; ++k) acc[i][j][k] = 0.f;

    load_stage(0, 0); asm volatile("cp.async.commit_group;");
    load_stage(1, 1); asm volatile("cp.async.commit_group;");

    for (int it = 0; it < NCHUNK; ++it) {
        const int st = it % 3;
        asm volatile("cp.async.wait_group 1;");
        __syncthreads();
        const uint32_t stb = sb + 1024 + st * 32768;
        #pragma unroll
        for (int ks = 0; ks < 4; ++ks) {
            const uint32_t kb = ks * 32;
            uint32_t a[2][4], b[8][2];
            #pragma unroll
            for (int mi = 0; mi < 2; ++mi)
                ldmx4(a[mi], stb + sw128(aoff + mi * 16 * 128 + kb));
            #pragma unroll
            for (int nj = 0; nj < 4; ++nj) {
                uint32_t r[4];
                ldmx4(r, stb + 16384 + sw128(boff0 + nj * 16 * 128 + kb));
                b[nj*2][0] = r[0]; b[nj*2][1] = r[1];
                b[nj*2+1][0] = r[2]; b[nj*2+1][1] = r[3];
            }
            #pragma unroll
            for (int mi = 0; mi < 2; ++mi)
                #pragma unroll
                for (int nf = 0; nf < 8; ++nf)
                    mma_hf(acc[mi][nf], a[mi], b[nf]);
        }
        if (it + 2 < NCHUNK) load_stage((it + 2) % 3, it + 2);
        asm volatile("cp.async.commit_group;");
    }

    #pragma unroll
    for (int mi = 0; mi < 2; ++mi) {
        #pragma unroll
        for (int h = 0; h < 2; ++h) {
            const int rl = wm + mi * 16 + (lane >> 2) + h * 8;
            const int slot = rows[rl];
            if (slot < 0) continue;
            #pragma unroll
            for (int nf = 0; nf < 8; ++nf) {
                const int gc = nBase + wn + nf * 8 + (lane & 3) * 2;
                const float v0 = acc[mi][nf][h*2], v1 = acc[mi][nf][h*2+1];
                if (MODE == 1) {
                    float a0 = v0 + bias[(size_t)e * HID + gc];
                    float a1 = v1 + bias[(size_t)e * HID + gc + 1];
                    a0 = a0 > 0.f ? a0 : 0.f;
                    a1 = a1 > 0.f ? a1 : 0.f;
                    *(__half2*)(g_ah + (size_t)slot * HID + gc) = __floats2half2_rn(a0, a1);
                } else {
                    float2 o = make_float2(v0 + bias[(size_t)e * DIM + gc],
                                           v1 + bias[(size_t)e * DIM + gc + 1]);
                    *(float2*)(g_eo + (size_t)slot * DIM + gc) = o;
                }
            }
        }
    }
}

// ---------------- head GEMM: fp16 single-pass, 3-stage pipe, 2 CTA/SM ----------------
__global__ void __launch_bounds__(256, 2) head_mma_kernel(const float* __restrict__ bias,
                                                          float* __restrict__ outp) {
    constexpr int NCHUNK = DIM / 64;
    extern __shared__ char smem[];
    const int tid = threadIdx.x;
    const int rowBase = blockIdx.x * 128, nBase = blockIdx.y * 128;
    const uint32_t sb = (uint32_t)__cvta_generic_to_shared(smem);

    auto load_stage = [&](int st, int chunk) {
        const uint32_t stb = sb + 1024 + st * 32768;
        const int k0 = chunk * 64;
        #pragma unroll
        for (int t = 0; t < 4; ++t) {
            int c = tid + t * 256, r = c >> 3, q = c & 7;
            uint32_t so = sw128((uint32_t)(r * 128 + q * 16));
            cpa16(stb + so,         g_ynh + (size_t)(rowBase + r) * DIM + k0 + q * 8);
            cpa16(stb + 16384 + so, g_Whf + (size_t)(nBase + r) * DIM + k0 + q * 8);
        }
    };

    const int lane = tid & 31, wid = tid >> 5;
    const int wm = (wid & 3) * 32, wn = (wid >> 2) * 64;
    const uint32_t aoff = (uint32_t)((wm + (lane & 15)) * 128 + (lane >> 4) * 16);
    const uint32_t boff0 = (uint32_t)((wn + ((lane >> 4) << 3) + (lane & 7)) * 128 +
                                      ((lane >> 3) & 1) * 16);

    float acc[2][8][4];
    #pragma unroll
    for (int i = 0; i < 2; ++i)
        #pragma unroll
        for (int j = 0; j < 8; ++j)
            #pragma unroll
            for (int k = 0; k < 4; ++k) acc[i][j][k] = 0.f;

    load_stage(0, 0); asm volatile("cp.async.commit_group;");
    load_stage(1, 1); asm volatile("cp.async.commit_group;");

    for (int it = 0; it < NCHUNK; ++it) {
        const int st = it % 3;
        asm volatile("cp.async.wait_group 1;");
        __syncthreads();
        const uint32_t stb = sb + 1024 + st * 32768;
        #pragma unroll
        for (int ks = 0; ks < 4; ++ks) {
            const uint32_t kb = ks * 32;
            uint32_t a[2][4], b[8][2];
            #pragma unroll
            for (int mi = 0; mi < 2; ++mi)
                ldmx4(a[mi], stb + sw128(aoff + mi * 16 * 128 + kb));
            #pragma unroll
            for (int nj = 0; nj < 4; ++nj) {
                uint32_t r[4];
                ldmx4(r, stb + 16384 + sw128(boff0 + nj * 16 * 128 + kb));
                b[nj*2][0] = r[0]; b[nj*2][1] = r[1];
                b[nj*2+1][0] = r[2]; b[nj*2+1][1] = r[3];
            }
            #pragma unroll
            for (int mi = 0; mi < 2; ++mi)
                #pragma unroll
                for (int nf = 0; nf < 8; ++nf)
                    mma_hf(acc[mi][nf], a[mi], b[nf]);
        }
        if (it + 2 < NCHUNK) load_stage((it + 2) % 3, it + 2);
        asm volatile("cp.async.commit_group;");
    }

    #pragma unroll
    for (int mi = 0; mi < 2; ++mi)
        #pragma unroll
        for (int h = 0; h < 2; ++h) {
            const int rl = wm + mi * 16 + (lane >> 2) + h * 8;
            #pragma unroll
            for (int nf = 0; nf < 8; ++nf) {
                const int gc = nBase + wn + nf * 8 + (lane & 3) * 2;
                float2 o = make_float2(acc[mi][nf][h*2]   + bias[gc],
                                       acc[mi][nf][h*2+1] + bias[gc+1]);
                *(float2*)(outp + (size_t)(rowBase + rl) * VOC + gc) = o;
            }
        }
}

// ---------------- combine gates + LayerNorm (-> yn fp16); re-zeroes g_count ----------------
__global__ void combine_ln_kernel(const float* __restrict__ ln_g,
                                  const float* __restrict__ ln_b) {
    const int n = blockIdx.x, tid = threadIdx.x;
    const float* e0 = g_eo + (size_t)n * 2 * DIM;
    const float* e1 = e0 + DIM;
    const float tv0 = g_tv[n*2+0], tv1 = g_tv[n*2+1];
    float y[DIM / 256], s = 0.f, ss = 0.f;
    #pragma unroll
    for (int q = 0; q < DIM / 256; ++q) {
        int d = tid + q * 256;
        float v = fmaf(tv0, e0[d], tv1 * e1[d]);
        y[q] = v; s += v; ss = fmaf(v, v, ss);
    }
    __shared__ float rs[8], rss[8];
    #pragma unroll
    for (int o = 16; o > 0; o >>= 1) {
        s  += __shfl_xor_sync(0xffffffffu, s, o);
        ss += __shfl_xor_sync(0xffffffffu, ss, o);
    }
    const int w = tid >> 5, lane = tid & 31;
    if (lane == 0) { rs[w] = s; rss[w] = ss; }
    __syncthreads();
    if (w == 0) {
        s  = (lane < 8) ? rs[lane]  : 0.f;
        ss = (lane < 8) ? rss[lane] : 0.f;
        #pragma unroll
        for (int o = 4; o > 0; o >>= 1) {
            s  += __shfl_xor_sync(0xffffffffu, s, o);
            ss += __shfl_xor_sync(0xffffffffu, ss, o);
        }
        if (lane == 0) { rs[0] = s; rss[0] = ss; }
    }
    __syncthreads();
    const float mu  = rs[0] * (1.f / DIM);
    const float var = rss[0] * (1.f / DIM) - mu * mu;
    const float inv = rsqrtf(var + LN_EPS);
    #pragma unroll
    for (int q = 0; q < DIM / 256; ++q) {
        int d = tid + q * 256;
        float v = fmaf((y[q] - mu) * inv, ln_g[d], ln_b[d]);
        g_ynh[(size_t)n * DIM + d] = __float2half(v);
    }
    // maintain replay invariant: counts are zero at the start of every launch
    if (n == 0 && tid < NEXP) g_count[tid] = 0;
}

// ---------------- launch: dual-stream event DAG (graph-capturable) ----------------
extern "C" void kernel_launch(void* const* d_in, const int* in_sizes, int n_in,
                              void* d_out, int out_size) {
    const int*   x       = (const int*)  d_in[0];
    const float* embed_W = (const float*)d_in[1];
    const float* gate_W  = (const float*)d_in[2];
    const float* gate_b  = (const float*)d_in[3];
    const float* W1      = (const float*)d_in[4];
    const float* b1      = (const float*)d_in[5];
    const float* W2      = (const float*)d_in[6];
    const float* b2      = (const float*)d_in[7];
    const float* ln_g    = (const float*)d_in[8];
    const float* ln_b    = (const float*)d_in[9];
    const float* head_W  = (const float*)d_in[10];
    const float* head_b  = (const float*)d_in[11];
    float* out = (float*)d_out;

    static cudaStream_t s2 = nullptr;
    static cudaEvent_t e0 = nullptr, e1 = nullptr, e2 = nullptr;
    static int init_done = 0;
    if (!init_done) {
        cudaFuncSetAttribute(moe_mma_kernel<1, DIM, HID>,
                             cudaFuncAttributeMaxDynamicSharedMemorySize, GEMM_SMEM);
        cudaFuncSetAttribute(moe_mma_kernel<2, HID, DIM>,
                             cudaFuncAttributeMaxDynamicSharedMemorySize, GEMM_SMEM);
        cudaFuncSetAttribute(head_mma_kernel,
                             cudaFuncAttributeMaxDynamicSharedMemorySize, GEMM_SMEM);
        cudaStreamCreateWithFlags(&s2, cudaStreamNonBlocking);
        cudaEventCreateWithFlags(&e0, cudaEventDisableTiming);
        cudaEventCreateWithFlags(&e1, cudaEventDisableTiming);
        cudaEventCreateWithFlags(&e2, cudaEventDisableTiming);
        init_done = 1;
    }

    const long long need_idx = (long long)NTOK * VOC + (long long)NTOK * 2;
    int write_idx = ((long long)out_size >= need_idx) ? 1 : 0;

    // fork side stream
    cudaEventRecord(e0, 0);
    cudaStreamWaitEvent(s2, e0, 0);

    // side stream: W1 transpose, then W2 transpose + head_W conversion
    conv_transpose_kernel<1><<<dim3(HID / 32, DIM / 32, NEXP), dim3(32, 8), 0, s2>>>(
        W1, DIM, HID);
    cudaEventRecord(e1, s2);
    conv_transpose_kernel<2><<<dim3(DIM / 32, HID / 32, NEXP), dim3(32, 8), 0, s2>>>(
        W2, HID, DIM);
    conv_half_kernel<<<(VOC * DIM / 4 + 255) / 256, 256, 0, s2>>>(
        (const float4*)head_W, (long)VOC * DIM / 4);
    cudaEventRecord(e2, s2);

    // main stream: routing/embed runs concurrently with convT1
    embed_gate_kernel<<<NTOK, 256>>>(x, embed_W, gate_W, gate_b, out, write_idx);

    cudaStreamWaitEvent(0, e1, 0);   // gemm1 needs g_W1h
    moe_mma_kernel<1, DIM, HID><<<dim3(HID / 128, NTOK / 128, NEXP), 256, GEMM_SMEM>>>(b1);

    cudaStreamWaitEvent(0, e2, 0);   // gemm2 needs g_W2h; head needs g_Whf (covered)
    moe_mma_kernel<2, HID, DIM><<<dim3(DIM / 128, NTOK / 128, NEXP), 256, GEMM_SMEM>>>(b2);
    combine_ln_kernel<<<NTOK, 256>>>(ln_g, ln_b);
    head_mma_kernel<<<dim3(NTOK / 128, VOC / 128), 256, GEMM_SMEM>>>(head_b, out);
}

// round 15
// speedup vs baseline: 1.3771x; 1.0103x over previous
#include <cuda_runtime.h>
#include <cuda_fp16.h>
#include <cstdint>

#define NTOK 4096
#define DIM  1024
#define HID  2048
#define NEXP 8
#define VOC  32000
#define LN_EPS 1e-5f
#define GEMM_SMEM (1024 + 3 * 32 * 1024)   // rows[]/pad + 3 stages * (A 16K + B 16K)

// ---------------- device-global scratch ----------------
__device__ __half g_hh [(size_t)NTOK * DIM];            // embeddings fp16
__device__ __half g_ah [(size_t)NTOK * 2 * HID];        // expert act fp16 per slot
__device__ float  g_eo [(size_t)NTOK * 2 * DIM];        // expert out fp32 per slot
__device__ __half g_ynh[(size_t)NTOK * DIM];            // layernormed fp16
__device__ __half g_Whf[(size_t)VOC * DIM];             // head_W fp16
__device__ __half g_W1h[(size_t)NEXP * HID * DIM];      // W1^T fp16 [E][N][K]
__device__ __half g_W2h[(size_t)NEXP * DIM * HID];      // W2^T fp16 [E][N][K]
__device__ float g_tv[NTOK * 2];
__device__ int   g_list[NEXP * NTOK];
__device__ int   g_count[NEXP];                         // zeroed at end of combine_ln

// ---------------- helpers ----------------
__device__ __forceinline__ uint32_t sw128(uint32_t o) { return o ^ ((o >> 3) & 0x70); }
__device__ __forceinline__ void cpa16(uint32_t d, const void* s) {
    asm volatile("cp.async.cg.shared.global [%0], [%1], 16;" :: "r"(d), "l"(s));
}
__device__ __forceinline__ void ldmx4(uint32_t* r, uint32_t a) {
    asm volatile("ldmatrix.sync.aligned.m8n8.x4.shared.b16 {%0,%1,%2,%3}, [%4];"
                 : "=r"(r[0]), "=r"(r[1]), "=r"(r[2]), "=r"(r[3]) : "r"(a));
}
__device__ __forceinline__ void mma_hf(float* c, const uint32_t* a, const uint32_t* b) {
    asm volatile("mma.sync.aligned.m16n8k16.row.col.f32.f16.f16.f32 "
                 "{%0,%1,%2,%3},{%4,%5,%6,%7},{%8,%9},{%0,%1,%2,%3};"
                 : "+f"(c[0]), "+f"(c[1]), "+f"(c[2]), "+f"(c[3])
                 : "r"(a[0]), "r"(a[1]), "r"(a[2]), "r"(a[3]), "r"(b[0]), "r"(b[1]));
}

// ---------------- small kernels ----------------
__global__ void conv_half_kernel(const float4* __restrict__ in, long n4) {
    long i = (long)blockIdx.x * blockDim.x + threadIdx.x;
    if (i >= n4) return;
    float4 v = in[i];
    __half2* o = (__half2*)g_Whf;
    o[i*2+0] = __floats2half2_rn(v.x, v.y);
    o[i*2+1] = __floats2half2_rn(v.z, v.w);
}

// in: [E][K][N] fp32 -> out fp16: [E][N][K].  Tile: 64 K-rows x 32 N-cols.
// Each thread writes one __half2 (two adjacent K elems) -> full 128B store lines.
template<int WSEL>
__global__ void conv_transpose_kernel(const float* __restrict__ in, int K, int N) {
    __shared__ float t[64][33];
    const int e = blockIdx.z;
    const float* pin = in + (size_t)e * K * N;
    __half* ph = (WSEL == 1 ? g_W1h : g_W2h) + (size_t)e * K * N;
    const int nb = blockIdx.x * 32, kb = blockIdx.y * 64;
    const int tx = threadIdx.x, ty = threadIdx.y;
    #pragma unroll
    for (int i = 0; i < 64; i += 8)
        t[ty + i][tx] = pin[(size_t)(kb + ty + i) * N + nb + tx];
    __syncthreads();
    #pragma unroll
    for (int i = 0; i < 32; i += 8) {
        const int n = nb + ty + i;
        __half2 h = __floats2half2_rn(t[2 * tx][ty + i], t[2 * tx + 1][ty + i]);
        *(__half2*)(ph + (size_t)n * K + kb + 2 * tx) = h;
    }
}

__global__ void embed_gate_kernel(const int* __restrict__ x,
                                  const float* __restrict__ embed_W,
                                  const float* __restrict__ gate_W,
                                  const float* __restrict__ gate_b,
                                  float* __restrict__ out, int write_idx) {
    __shared__ float sh[DIM];
    __shared__ float slogit[NEXP];
    const int n = blockIdx.x, tid = threadIdx.x;
    const float* erow = embed_W + (size_t)x[n] * DIM;
    #pragma unroll
    for (int q = 0; q < DIM / 256; ++q) {
        int d = tid + q * 256;
        float v = erow[d];
        sh[d] = v;
        g_hh[(size_t)n * DIM + d] = __float2half(v);
    }
    __syncthreads();
    const int w = tid >> 5, lane = tid & 31;
    const float* gw = gate_W + (size_t)w * DIM;
    float acc = 0.f;
    for (int d = lane; d < DIM; d += 32) acc = fmaf(sh[d], gw[d], acc);
    #pragma unroll
    for (int o = 16; o > 0; o >>= 1) acc += __shfl_xor_sync(0xffffffffu, acc, o);
    if (lane == 0) slogit[w] = acc + gate_b[w];
    __syncthreads();
    if (tid == 0) {
        float mx = slogit[0];
        #pragma unroll
        for (int e = 1; e < NEXP; ++e) mx = fmaxf(mx, slogit[e]);
        float p[NEXP], s = 0.f;
        #pragma unroll
        for (int e = 0; e < NEXP; ++e) { p[e] = expf(slogit[e] - mx); s += p[e]; }
        float inv = 1.f / s;
        #pragma unroll
        for (int e = 0; e < NEXP; ++e) p[e] *= inv;
        int i0 = 0; float v0 = p[0];
        #pragma unroll
        for (int e = 1; e < NEXP; ++e) if (p[e] > v0) { v0 = p[e]; i0 = e; }
        int i1 = -1; float v1 = -1.f;
        #pragma unroll
        for (int e = 0; e < NEXP; ++e) {
            if (e != i0 && p[e] > v1) { v1 = p[e]; i1 = e; }
        }
        g_tv[n*2+0] = v0; g_tv[n*2+1] = v1;
        int p0 = atomicAdd(&g_count[i0], 1); g_list[i0 * NTOK + p0] = n*2;
        int p1 = atomicAdd(&g_count[i1], 1); g_list[i1 * NTOK + p1] = n*2+1;
        if (write_idx) {
            out[(size_t)NTOK * VOC + n*2+0] = (float)i0;
            out[(size_t)NTOK * VOC + n*2+1] = (float)i1;
        }
    }
}

// ---------------- expert HMMA GEMM (fp16 single-pass, fp32 accum) ----------------
// D tile 128x128, 8 warps (warp 32x64), K-chunk 64, 3-stage cp.async, 2 CTA/SM.
// MODE 1: relu(h W1+b1) -> g_ah fp16; MODE 2: a W2+b2 -> g_eo fp32
template<int MODE, int KTOT, int NTOT>
__global__ void __launch_bounds__(256, 2) moe_mma_kernel(const float* __restrict__ bias) {
    constexpr int NCHUNK = KTOT / 64;
    extern __shared__ char smem[];
    const int tid = threadIdx.x;

    const int mt = blockIdx.y, nt = blockIdx.x, e = blockIdx.z;
    if (mt * 128 >= g_count[e]) return;
    const int rowBase = mt * 128, nBase = nt * 128;
    const uint32_t sb = (uint32_t)__cvta_generic_to_shared(smem);
    int* rows = (int*)smem;
    if (tid < 128) {
        int r = rowBase + tid;
        rows[tid] = (r < g_count[e]) ? g_list[e * NTOK + r] : -1;
    }
    __syncthreads();

    const __half* A = (MODE == 1) ? g_hh : g_ah;
    const __half* B = ((MODE == 1) ? g_W1h : g_W2h)
                      + (size_t)e * KTOT * NTOT + (size_t)nBase * KTOT;

    auto load_stage = [&](int st, int chunk) {
        const uint32_t stb = sb + 1024 + st * 32768;
        const int k0 = chunk * 64;
        #pragma unroll
        for (int t = 0; t < 4; ++t) {
            int c = tid + t * 256, r = c >> 3, q = c & 7;
            int s = rows[r]; if (s < 0) s = rows[0];
            size_t ro = (MODE == 1 ? (size_t)(s >> 1) : (size_t)s) * KTOT + k0 + q * 8;
            uint32_t so = sw128((uint32_t)(r * 128 + q * 16));
            cpa16(stb + so,         A + ro);
            cpa16(stb + 16384 + so, B + (size_t)r * KTOT + k0 + q * 8);
        }
    };

    const int lane = tid & 31, wid = tid >> 5;
    const int wm = (wid & 3) * 32, wn = (wid >> 2) * 64;
    const uint32_t aoff = (uint32_t)((wm + (lane & 15)) * 128 + (lane >> 4) * 16);
    const uint32_t boff0 = (uint32_t)((wn + ((lane >> 4) << 3) + (lane & 7)) * 128 +
                                      ((lane >> 3) & 1) * 16);

    float acc[2][8][4];
    #pragma unroll
    for (int i = 0; i < 2; ++i)
        #pragma unroll
        for (int j = 0; j < 8; ++j)
            #pragma unroll
            for (int k = 0; k < 4; ++k) acc[i][j][k] = 0.f;

    load_stage(0, 0); asm volatile("cp.async.commit_group;");
    load_stage(1, 1); asm volatile("cp.async.commit_group;");

    for (int it = 0; it < NCHUNK; ++it) {
        const int st = it % 3;
        asm volatile("cp.async.wait_group 1;");
        __syncthreads();
        const uint32_t stb = sb + 1024 + st * 32768;
        #pragma unroll
        for (int ks = 0; ks < 4; ++ks) {
            const uint32_t kb = ks * 32;
            uint32_t a[2][4], b[8][2];
            #pragma unroll
            for (int mi = 0; mi < 2; ++mi)
                ldmx4(a[mi], stb + sw128(aoff + mi * 16 * 128 + kb));
            #pragma unroll
            for (int nj = 0; nj < 4; ++nj) {
                uint32_t r[4];
                ldmx4(r, stb + 16384 + sw128(boff0 + nj * 16 * 128 + kb));
                b[nj*2][0] = r[0]; b[nj*2][1] = r[1];
                b[nj*2+1][0] = r[2]; b[nj*2+1][1] = r[3];
            }
            #pragma unroll
            for (int mi = 0; mi < 2; ++mi)
                #pragma unroll
                for (int nf = 0; nf < 8; ++nf)
                    mma_hf(acc[mi][nf], a[mi], b[nf]);
        }
        if (it + 2 < NCHUNK) load_stage((it + 2) % 3, it + 2);
        asm volatile("cp.async.commit_group;");
    }

    #pragma unroll
    for (int mi = 0; mi < 2; ++mi) {
        #pragma unroll
        for (int h = 0; h < 2; ++h) {
            const int rl = wm + mi * 16 + (lane >> 2) + h * 8;
            const int slot = rows[rl];
            if (slot < 0) continue;
            #pragma unroll
            for (int nf = 0; nf < 8; ++nf) {
                const int gc = nBase + wn + nf * 8 + (lane & 3) * 2;
                const float v0 = acc[mi][nf][h*2], v1 = acc[mi][nf][h*2+1];
                if (MODE == 1) {
                    float a0 = v0 + bias[(size_t)e * HID + gc];
                    float a1 = v1 + bias[(size_t)e * HID + gc + 1];
                    a0 = a0 > 0.f ? a0 : 0.f;
                    a1 = a1 > 0.f ? a1 : 0.f;
                    *(__half2*)(g_ah + (size_t)slot * HID + gc) = __floats2half2_rn(a0, a1);
                } else {
                    float2 o = make_float2(v0 + bias[(size_t)e * DIM + gc],
                                           v1 + bias[(size_t)e * DIM + gc + 1]);
                    *(float2*)(g_eo + (size_t)slot * DIM + gc) = o;
                }
            }
        }
    }
}

// ---------------- head GEMM: fp16 single-pass, 3-stage pipe, 2 CTA/SM ----------------
__global__ void __launch_bounds__(256, 2) head_mma_kernel(const float* __restrict__ bias,
                                                          float* __restrict__ outp) {
    constexpr int NCHUNK = DIM / 64;
    extern __shared__ char smem[];
    const int tid = threadIdx.x;
    const int rowBase = blockIdx.x * 128, nBase = blockIdx.y * 128;
    const uint32_t sb = (uint32_t)__cvta_generic_to_shared(smem);

    auto load_stage = [&](int st, int chunk) {
        const uint32_t stb = sb + 1024 + st * 32768;
        const int k0 = chunk * 64;
        #pragma unroll
        for (int t = 0; t < 4; ++t) {
            int c = tid + t * 256, r = c >> 3, q = c & 7;
            uint32_t so = sw128((uint32_t)(r * 128 + q * 16));
            cpa16(stb + so,         g_ynh + (size_t)(rowBase + r) * DIM + k0 + q * 8);
            cpa16(stb + 16384 + so, g_Whf + (size_t)(nBase + r) * DIM + k0 + q * 8);
        }
    };

    const int lane = tid & 31, wid = tid >> 5;
    const int wm = (wid & 3) * 32, wn = (wid >> 2) * 64;
    const uint32_t aoff = (uint32_t)((wm + (lane & 15)) * 128 + (lane >> 4) * 16);
    const uint32_t boff0 = (uint32_t)((wn + ((lane >> 4) << 3) + (lane & 7)) * 128 +
                                      ((lane >> 3) & 1) * 16);

    float acc[2][8][4];
    #pragma unroll
    for (int i = 0; i < 2; ++i)
        #pragma unroll
        for (int j = 0; j < 8; ++j)
            #pragma unroll
            for (int k = 0; k < 4; ++k) acc[i][j][k] = 0.f;

    load_stage(0, 0); asm volatile("cp.async.commit_group;");
    load_stage(1, 1); asm volatile("cp.async.commit_group;");

    for (int it = 0; it < NCHUNK; ++it) {
        const int st = it % 3;
        asm volatile("cp.async.wait_group 1;");
        __syncthreads();
        const uint32_t stb = sb + 1024 + st * 32768;
        #pragma unroll
        for (int ks = 0; ks < 4; ++ks) {
            const uint32_t kb = ks * 32;
            uint32_t a[2][4], b[8][2];
            #pragma unroll
            for (int mi = 0; mi < 2; ++mi)
                ldmx4(a[mi], stb + sw128(aoff + mi * 16 * 128 + kb));
            #pragma unroll
            for (int nj = 0; nj < 4; ++nj) {
                uint32_t r[4];
                ldmx4(r, stb + 16384 + sw128(boff0 + nj * 16 * 128 + kb));
                b[nj*2][0] = r[0]; b[nj*2][1] = r[1];
                b[nj*2+1][0] = r[2]; b[nj*2+1][1] = r[3];
            }
            #pragma unroll
            for (int mi = 0; mi < 2; ++mi)
                #pragma unroll
                for (int nf = 0; nf < 8; ++nf)
                    mma_hf(acc[mi][nf], a[mi], b[nf]);
        }
        if (it + 2 < NCHUNK) load_stage((it + 2) % 3, it + 2);
        asm volatile("cp.async.commit_group;");
    }

    #pragma unroll
    for (int mi = 0; mi < 2; ++mi)
        #pragma unroll
        for (int h = 0; h < 2; ++h) {
            const int rl = wm + mi * 16 + (lane >> 2) + h * 8;
            #pragma unroll
            for (int nf = 0; nf < 8; ++nf) {
                const int gc = nBase + wn + nf * 8 + (lane & 3) * 2;
                float2 o = make_float2(acc[mi][nf][h*2]   + bias[gc],
                                       acc[mi][nf][h*2+1] + bias[gc+1]);
                *(float2*)(outp + (size_t)(rowBase + rl) * VOC + gc) = o;
            }
        }
}

// ---------------- combine gates + LayerNorm (-> yn fp16); re-zeroes g_count ----------------
__global__ void combine_ln_kernel(const float* __restrict__ ln_g,
                                  const float* __restrict__ ln_b) {
    const int n = blockIdx.x, tid = threadIdx.x;
    const float* e0 = g_eo + (size_t)n * 2 * DIM;
    const float* e1 = e0 + DIM;
    const float tv0 = g_tv[n*2+0], tv1 = g_tv[n*2+1];
    float y[DIM / 256], s = 0.f, ss = 0.f;
    #pragma unroll
    for (int q = 0; q < DIM / 256; ++q) {
        int d = tid + q * 256;
        float v = fmaf(tv0, e0[d], tv1 * e1[d]);
        y[q] = v; s += v; ss = fmaf(v, v, ss);
    }
    __shared__ float rs[8], rss[8];
    #pragma unroll
    for (int o = 16; o > 0; o >>= 1) {
        s  += __shfl_xor_sync(0xffffffffu, s, o);
        ss += __shfl_xor_sync(0xffffffffu, ss, o);
    }
    const int w = tid >> 5, lane = tid & 31;
    if (lane == 0) { rs[w] = s; rss[w] = ss; }
    __syncthreads();
    if (w == 0) {
        s  = (lane < 8) ? rs[lane]  : 0.f;
        ss = (lane < 8) ? rss[lane] : 0.f;
        #pragma unroll
        for (int o = 4; o > 0; o >>= 1) {
            s  += __shfl_xor_sync(0xffffffffu, s, o);
            ss += __shfl_xor_sync(0xffffffffu, ss, o);
        }
        if (lane == 0) { rs[0] = s; rss[0] = ss; }
    }
    __syncthreads();
    const float mu  = rs[0] * (1.f / DIM);
    const float var = rss[0] * (1.f / DIM) - mu * mu;
    const float inv = rsqrtf(var + LN_EPS);
    #pragma unroll
    for (int q = 0; q < DIM / 256; ++q) {
        int d = tid + q * 256;
        float v = fmaf((y[q] - mu) * inv, ln_g[d], ln_b[d]);
        g_ynh[(size_t)n * DIM + d] = __float2half(v);
    }
    // maintain replay invariant: counts are zero at the start of every launch
    if (n == 0 && tid < NEXP) g_count[tid] = 0;
}

// ---------------- launch: dual-stream event DAG (graph-capturable) ----------------
extern "C" void kernel_launch(void* const* d_in, const int* in_sizes, int n_in,
                              void* d_out, int out_size) {
    const int*   x       = (const int*)  d_in[0];
    const float* embed_W = (const float*)d_in[1];
    const float* gate_W  = (const float*)d_in[2];
    const float* gate_b  = (const float*)d_in[3];
    const float* W1      = (const float*)d_in[4];
    const float* b1      = (const float*)d_in[5];
    const float* W2      = (const float*)d_in[6];
    const float* b2      = (const float*)d_in[7];
    const float* ln_g    = (const float*)d_in[8];
    const float* ln_b    = (const float*)d_in[9];
    const float* head_W  = (const float*)d_in[10];
    const float* head_b  = (const float*)d_in[11];
    float* out = (float*)d_out;

    static cudaStream_t s2 = nullptr;
    static cudaEvent_t e0 = nullptr, e1 = nullptr, e2 = nullptr;
    static int init_done = 0;
    if (!init_done) {
        cudaFuncSetAttribute(moe_mma_kernel<1, DIM, HID>,
                             cudaFuncAttributeMaxDynamicSharedMemorySize, GEMM_SMEM);
        cudaFuncSetAttribute(moe_mma_kernel<2, HID, DIM>,
                             cudaFuncAttributeMaxDynamicSharedMemorySize, GEMM_SMEM);
        cudaFuncSetAttribute(head_mma_kernel,
                             cudaFuncAttributeMaxDynamicSharedMemorySize, GEMM_SMEM);
        cudaStreamCreateWithFlags(&s2, cudaStreamNonBlocking);
        cudaEventCreateWithFlags(&e0, cudaEventDisableTiming);
        cudaEventCreateWithFlags(&e1, cudaEventDisableTiming);
        cudaEventCreateWithFlags(&e2, cudaEventDisableTiming);
        init_done = 1;
    }

    const long long need_idx = (long long)NTOK * VOC + (long long)NTOK * 2;
    int write_idx = ((long long)out_size >= need_idx) ? 1 : 0;

    // fork side stream
    cudaEventRecord(e0, 0);
    cudaStreamWaitEvent(s2, e0, 0);

    // side stream: W1 transpose, then W2 transpose + head_W conversion
    conv_transpose_kernel<1><<<dim3(HID / 32, DIM / 64, NEXP), dim3(32, 8), 0, s2>>>(
        W1, DIM, HID);
    cudaEventRecord(e1, s2);
    conv_transpose_kernel<2><<<dim3(DIM / 32, HID / 64, NEXP), dim3(32, 8), 0, s2>>>(
        W2, HID, DIM);
    conv_half_kernel<<<(VOC * DIM / 4 + 255) / 256, 256, 0, s2>>>(
        (const float4*)head_W, (long)VOC * DIM / 4);
    cudaEventRecord(e2, s2);

    // main stream: routing/embed runs concurrently with convT1
    embed_gate_kernel<<<NTOK, 256>>>(x, embed_W, gate_W, gate_b, out, write_idx);

    cudaStreamWaitEvent(0, e1, 0);   // gemm1 needs g_W1h
    moe_mma_kernel<1, DIM, HID><<<dim3(HID / 128, NTOK / 128, NEXP), 256, GEMM_SMEM>>>(b1);

    cudaStreamWaitEvent(0, e2, 0);   // gemm2 needs g_W2h; head needs g_Whf (covered)
    moe_mma_kernel<2, HID, DIM><<<dim3(DIM / 128, NTOK / 128, NEXP), 256, GEMM_SMEM>>>(b2);
    combine_ln_kernel<<<NTOK, 256>>>(ln_g, ln_b);
    head_mma_kernel<<<dim3(NTOK / 128, VOC / 128), 256, GEMM_SMEM>>>(head_b, out);
}